// round 15
// baseline (speedup 1.0000x reference)
#include <cuda_runtime.h>
#include <cstdint>

// out = e + (e @ B) @ A^T   with e:[16384,4096] f32, A,B:[4096,16] f32
// R15: single-DRAM-read-of-e design. Block owns 8 rows; the 128KB fp32 e-tile
// is staged to SMEM via cp.async and consumed by BOTH phases.
//  phase 1 (transposed): T[16rank x 8row] = Btfrag(A-op) x e^T(B-op), one
//    n=8 mma per kstep per warp; sigma k-perm -> lane reads one LDS.128 of e.
//  phase 2: identical to validated R11 path (paired n-tiles, g_Afrag2),
//    with t rows 8-15 zeroed (their outputs are never stored).
// Traffic: 768 MB -> 512 MB (read e once + write out).

#define MROWS 16384
#define DDIM  4096
#define RANK  16
#define ROWS_PER_BLK 8
#define ROWPITCH 4112            // 4096 + 16 floats pad (conflict-free phases)

// Phase-1 Bt fragments (A-operand): [kstep(256)][lane(32)] = {a0,a1,a2,a3}
__device__ __align__(16) uint4 g_BtfragT[256 * 32];
// Phase-2 A fragments (B-operand): [ct2(256)][lane(32)] = {t0lo,t0hi,t1lo,t1hi}
__device__ __align__(16) uint4 g_Afrag2[256 * 32];

static const int SMEM_E     = 0;
static const int SMEM_SACC  = ROWS_PER_BLK * ROWPITCH * 4;        // 131584
static const int SMEM_T     = SMEM_SACC + 8 * 32 * 4 * 4;         // +4096
static const int SMEM_TOTAL = SMEM_T + 16 * 8 * 4;                // +512

// pack two f32 -> bf16x2 (lo in low 16 bits)
__device__ __forceinline__ uint32_t pk_bf16(float lo, float hi) {
    uint32_t r;
    asm("cvt.rn.bf16x2.f32 %0, %1, %2;" : "=r"(r) : "f"(hi), "f"(lo));
    return r;
}

// D += A(16x16 bf16, row) * B(16x8 bf16, col), f32 accum (in-place)
__device__ __forceinline__ void mma_bf16(
    float& d0, float& d1, float& d2, float& d3,
    uint32_t a0, uint32_t a1, uint32_t a2, uint32_t a3,
    uint32_t b0, uint32_t b1) {
    asm("mma.sync.aligned.m16n8k16.row.col.f32.bf16.bf16.f32 "
        "{%0,%1,%2,%3},{%4,%5,%6,%7},{%8,%9},{%0,%1,%2,%3};"
        : "+f"(d0), "+f"(d1), "+f"(d2), "+f"(d3)
        : "r"(a0), "r"(a1), "r"(a2), "r"(a3), "r"(b0), "r"(b1));
}

// ---------------- k0: build bf16 fragments ----------------
// 24576 threads. First 8192: Bt frags (256 ksteps x 32 lanes).
// Next 16384: A frags (512 jobs x 32 lanes) — unchanged from R11.
__global__ __launch_bounds__(256) void k0_frags(const float* __restrict__ A,
                                                const float* __restrict__ B) {
    int t = blockIdx.x * 256 + threadIdx.x;
    int lane = t & 31;
    int g = lane >> 2, tg = lane & 3;
    if (t < 8192) {
        int kstep = t >> 5;
        int k = kstep * 16;
        // A-op rows = ranks: a0/a2 ranks g, a1/a3 ranks g+8.
        // sigma: frag k {2tg,2tg+1,2tg+8,2tg+9} -> global d {4tg..4tg+3}.
        uint32_t x = pk_bf16(B[(k + 4 * tg + 0) * RANK + g],
                             B[(k + 4 * tg + 1) * RANK + g]);
        uint32_t y = pk_bf16(B[(k + 4 * tg + 0) * RANK + g + 8],
                             B[(k + 4 * tg + 1) * RANK + g + 8]);
        uint32_t z = pk_bf16(B[(k + 4 * tg + 2) * RANK + g],
                             B[(k + 4 * tg + 3) * RANK + g]);
        uint32_t w = pk_bf16(B[(k + 4 * tg + 2) * RANK + g + 8],
                             B[(k + 4 * tg + 3) * RANK + g + 8]);
        g_BtfragT[(size_t)kstep * 32 + lane] = make_uint4(x, y, z, w);
    } else {
        int job = (t - 8192) >> 5;
        int ct2 = job >> 1, tile = job & 1;
        int c = ct2 * 16 + 4 * (g >> 1) + 2 * tile + (g & 1);
        uint32_t lo = pk_bf16(A[(size_t)c * RANK + 2 * tg],
                              A[(size_t)c * RANK + 2 * tg + 1]);
        uint32_t hi = pk_bf16(A[(size_t)c * RANK + 2 * tg + 8],
                              A[(size_t)c * RANK + 2 * tg + 9]);
        reinterpret_cast<unsigned long long*>(g_Afrag2)
            [(size_t)(ct2 * 32 + lane) * 2 + tile] =
            ((unsigned long long)hi << 32) | lo;
    }
}

// ---------------- fused main kernel ----------------
// grid 2048, block 256 (8 warps). Block owns 8 rows. occ 1 (136KB smem).
__global__ __launch_bounds__(256) void fused_smem(const float* __restrict__ e,
                                                  float* __restrict__ out) {
    extern __shared__ __align__(16) char smem_raw[];
    float* e_s   = reinterpret_cast<float*>(smem_raw + SMEM_E);
    float* sacc  = reinterpret_cast<float*>(smem_raw + SMEM_SACC);
    float* t_f32 = reinterpret_cast<float*>(smem_raw + SMEM_T);

    const int tid  = threadIdx.x;
    const int wid  = tid >> 5;
    const int lane = tid & 31;
    const int g    = lane >> 2;
    const int tg   = lane & 3;
    const int blkrow = blockIdx.x * ROWS_PER_BLK;

    // ---- stage e tile (8 x 4096 f32 = 128KB) via cp.async ----
    {
        const float* gbase = e + (size_t)blkrow * DDIM;
#pragma unroll 8
        for (int it = 0; it < 32; it++) {
            int idx = it * 256 + tid;      // 0..8191 float4 slots
            int r  = idx >> 10;            // row 0..7
            int c4 = idx & 1023;           // float4 within row
            uint32_t dst = (uint32_t)__cvta_generic_to_shared(
                e_s + r * ROWPITCH + c4 * 4);
            const float* src = gbase + (size_t)r * DDIM + c4 * 4;
            asm volatile("cp.async.cg.shared.global [%0], [%1], 16;\n"
                         :: "r"(dst), "l"(src));
        }
        asm volatile("cp.async.commit_group;\n");
        asm volatile("cp.async.wait_group 0;\n");
    }
    __syncthreads();

    // ---- phase 1: T[16rank][8row]; warp w does ksteps [w*32, w*32+32) ----
    {
        float d0 = 0.f, d1 = 0.f, d2 = 0.f, d3 = 0.f;
        const uint4* btf = g_BtfragT + (size_t)(wid * 32) * 32 + lane;
        const float* ep = e_s + g * ROWPITCH + tg * 4;
#pragma unroll 4
        for (int j = 0; j < 32; j++) {
            uint4 af = btf[(size_t)j * 32];
            float4 ev = *reinterpret_cast<const float4*>(
                ep + (wid * 32 + j) * 16);
            uint32_t b0 = pk_bf16(ev.x, ev.y);   // e[g][kb+4tg..+1]
            uint32_t b1 = pk_bf16(ev.z, ev.w);   // e[g][kb+4tg+2..+3]
            mma_bf16(d0, d1, d2, d3, af.x, af.y, af.z, af.w, b0, b1);
        }
        // store partial D-frag (float4, conflict-free)
        reinterpret_cast<float4*>(sacc)[wid * 32 + lane] =
            make_float4(d0, d1, d2, d3);
    }
    __syncthreads();

    // reduce 8 k-slices -> t_f32[rank][row]  ([16][8])
    if (tid < 32) {
        float s0 = 0.f, s1 = 0.f, s2 = 0.f, s3 = 0.f;
#pragma unroll
        for (int w = 0; w < 8; w++) {
            float4 v = reinterpret_cast<const float4*>(sacc)[w * 32 + tid];
            s0 += v.x; s1 += v.y; s2 += v.z; s3 += v.w;
        }
        // d0=T[g][2tg] d1=T[g][2tg+1] d2=T[g+8][2tg] d3=T[g+8][2tg+1]
        t_f32[g * 8 + 2 * tg]           = s0;
        t_f32[g * 8 + 2 * tg + 1]       = s1;
        t_f32[(g + 8) * 8 + 2 * tg]     = s2;
        t_f32[(g + 8) * 8 + 2 * tg + 1] = s3;
    }
    __syncthreads();

    // ---- phase 2: out = e + t @ A^T; warp w does double-tiles [w*32,+32) ----
    {
        // A-op of t: rows = e-rows (0..7 real, 8..15 zero), k = rank identity
        uint32_t ta0 = pk_bf16(t_f32[(2 * tg) * 8 + g],
                               t_f32[(2 * tg + 1) * 8 + g]);
        uint32_t ta2 = pk_bf16(t_f32[(2 * tg + 8) * 8 + g],
                               t_f32[(2 * tg + 9) * 8 + g]);

        const uint4* afp = g_Afrag2 + (size_t)(wid * 32) * 32 + lane;
        const float* ep = e_s + g * ROWPITCH + tg * 4;
        float* obase = out + (size_t)(blkrow + g) * DDIM + tg * 4;

#pragma unroll 4
        for (int j = 0; j < 32; j++) {
            uint4 af = afp[(size_t)j * 32];
            const int cbase = (wid * 32 + j) * 16;

            float4 ev = *reinterpret_cast<const float4*>(ep + cbase);
            float d0 = ev.x, d1 = ev.y, x2 = 0.f, x3 = 0.f;   // tile0, row g
            float q0 = ev.z, q1 = ev.w, y2 = 0.f, y3 = 0.f;   // tile1, row g

            mma_bf16(d0, d1, x2, x3, ta0, 0u, ta2, 0u, af.x, af.y);
            mma_bf16(q0, q1, y2, y3, ta0, 0u, ta2, 0u, af.z, af.w);

            *reinterpret_cast<float4*>(obase + cbase) =
                make_float4(d0, d1, q0, q1);
        }
    }
}

extern "C" void kernel_launch(void* const* d_in, const int* in_sizes, int n_in,
                              void* d_out, int out_size) {
    const float* e = (const float*)d_in[0];  // [4,4096,4096]
    const float* A = (const float*)d_in[1];  // [4096,16]
    const float* B = (const float*)d_in[2];  // [4096,16]
    float* out = (float*)d_out;

    (void)in_sizes; (void)n_in; (void)out_size;

    cudaFuncSetAttribute(fused_smem,
                         cudaFuncAttributeMaxDynamicSharedMemorySize,
                         SMEM_TOTAL);

    k0_frags<<<96, 256>>>(A, B);
    fused_smem<<<MROWS / ROWS_PER_BLK, 256, SMEM_TOTAL>>>(e, out);
}